// round 2
// baseline (speedup 1.0000x reference)
#include <cuda_runtime.h>
#include <cuda_bf16.h>
#include <math.h>

// NerfHash fused kernel, round 2: float4 (LDS.128) weight reads.
// Ragged layers padded at staging: fw3 [64,65]->[64,68], rw2 [64,3]->[64,4],
// biases padded with zeros so the padded lanes compute garbage-free values
// that are simply never written out.

#define LVLS 24
#define TSZ  (1u << 19)
#define P1   2654435761u
#define P2   805459861u

struct ResArr { float r[LVLS]; };
struct WPtrs  { const float* w[14]; };

// shared-memory float offsets (all multiples of 4 -> 16B aligned)
#define OFF_FW0 0        // 48*64 = 3072
#define OFF_FB0 3072     // 64
#define OFF_FW1 3136     // 64*64 = 4096
#define OFF_FB1 7232     // 64
#define OFF_FW2 7296     // 4096
#define OFF_FB2 11392    // 64
#define OFF_FW3 11456    // 64*68 = 4352 (padded from 64*65)
#define OFF_FB3 15808    // 68 (padded from 65)
#define OFF_RW0 15876    // 73*64 = 4672
#define OFF_RB0 20548    // 64
#define OFF_RW1 20612    // 4096
#define OFF_RB1 24708    // 64
#define OFF_RW2 24772    // 64*4 = 256 (padded from 64*3)
#define OFF_RB2 25028    // 4 (padded from 3)
#define SMEM_FLOATS 25032
#define SMEM_BYTES  (SMEM_FLOATS * 4)

__device__ __forceinline__ float gelu_exact(float x) {
    return 0.5f * x * (1.0f + erff(x * 0.70710678118654752440f));
}
__device__ __forceinline__ float softplus_f(float x) {
    return fmaxf(x, 0.0f) + log1pf(expf(-fabsf(x)));
}
__device__ __forceinline__ float sigmoid_f(float x) {
    return 1.0f / (1.0f + expf(-x));
}

// IN x OUTP dense layer; OUTP must be a multiple of 4 (padded), W is
// row-major [IN, OUTP] in shared, 16B aligned. Writes OUTP outputs.
template<int IN, int OUTP, bool ACT>
__device__ __forceinline__ void dense(const float* __restrict__ in,
                                      float* __restrict__ out,
                                      const float* __restrict__ W,
                                      const float* __restrict__ B) {
#pragma unroll
    for (int j0 = 0; j0 < OUTP; j0 += 32) {
        constexpr int CH = 32;
        const int width = (OUTP - 0 > 32) ? 32 : OUTP;   // OUTP<32 case
        (void)width;
        float acc[CH];
        const int lim = (OUTP - j0 < CH) ? (OUTP - j0) : CH;
#pragma unroll
        for (int jj = 0; jj < CH; jj++)
            if (jj < lim) acc[jj] = B[j0 + jj];
#pragma unroll 4
        for (int i = 0; i < IN; i++) {
            float v = in[i];
            const float4* Wr = (const float4*)(W + i * OUTP + j0);
#pragma unroll
            for (int q = 0; q < CH / 4; q++) {
                if (q * 4 < lim) {
                    float4 w4 = Wr[q];
                    acc[q * 4 + 0] = fmaf(v, w4.x, acc[q * 4 + 0]);
                    acc[q * 4 + 1] = fmaf(v, w4.y, acc[q * 4 + 1]);
                    acc[q * 4 + 2] = fmaf(v, w4.z, acc[q * 4 + 2]);
                    acc[q * 4 + 3] = fmaf(v, w4.w, acc[q * 4 + 3]);
                }
            }
        }
#pragma unroll
        for (int jj = 0; jj < CH; jj++)
            if (jj < lim) out[j0 + jj] = ACT ? gelu_exact(acc[jj]) : acc[jj];
    }
}

__global__ void __launch_bounds__(256)
nerf_fused_kernel(const float* __restrict__ pts,
                  const float* __restrict__ dirs,
                  const float* __restrict__ table,
                  WPtrs prm, ResArr res,
                  float* __restrict__ out, int n)
{
    extern __shared__ float s[];

    // ---- stage weights into shared (with zero-padded restriding) ----
    {
        // plain copies: fw0,fb0,fw1,fb1,fw2,fb2, rw0,rb0,rw1,rb1
        const float* src; int off, sz;
        const int plain_a[10]   = {0,1,2,3,4,5,8,9,10,11};
        const int plain_off[10] = {OFF_FW0,OFF_FB0,OFF_FW1,OFF_FB1,OFF_FW2,OFF_FB2,
                                   OFF_RW0,OFF_RB0,OFF_RW1,OFF_RB1};
        const int plain_sz[10]  = {3072,64,4096,64,4096,64,4672,64,4096,64};
#pragma unroll 1
        for (int a = 0; a < 10; a++) {
            src = prm.w[plain_a[a]]; off = plain_off[a]; sz = plain_sz[a];
            for (int k = threadIdx.x; k < sz; k += blockDim.x)
                s[off + k] = src[k];
        }
        // fw3: [64,65] -> [64,68] zero pad
        src = prm.w[6];
        for (int k = threadIdx.x; k < 64 * 68; k += blockDim.x) {
            int r = k / 68, c = k % 68;
            s[OFF_FW3 + k] = (c < 65) ? src[r * 65 + c] : 0.0f;
        }
        // fb3: 65 -> 68
        src = prm.w[7];
        for (int k = threadIdx.x; k < 68; k += blockDim.x)
            s[OFF_FB3 + k] = (k < 65) ? src[k] : 0.0f;
        // rw2: [64,3] -> [64,4]
        src = prm.w[12];
        for (int k = threadIdx.x; k < 64 * 4; k += blockDim.x) {
            int r = k / 4, c = k % 4;
            s[OFF_RW2 + k] = (c < 3) ? src[r * 3 + c] : 0.0f;
        }
        // rb2: 3 -> 4
        src = prm.w[13];
        for (int k = threadIdx.x; k < 4; k += blockDim.x)
            s[OFF_RB2 + k] = (k < 3) ? src[k] : 0.0f;
    }
    __syncthreads();

    int i = blockIdx.x * blockDim.x + threadIdx.x;
    if (i >= n) return;

    float px = pts[i * 3 + 0];
    float py = pts[i * 3 + 1];
    float pz = pts[i * 3 + 2];
    float x0 = (px + 1.0f) * 0.5f;
    float y0 = (py + 1.0f) * 0.5f;
    float z0 = (pz + 1.0f) * 0.5f;

    // ---- hash-grid encoding: enc[48] ----
    float enc[48];
#pragma unroll 1
    for (int l = 0; l < LVLS; l++) {
        float rl = res.r[l];
        float posx = x0 * rl, posy = y0 * rl, posz = z0 * rl;
        float fx = floorf(posx), fy = floorf(posy), fz = floorf(posz);
        float wx = posx - fx, wy = posy - fy, wz = posz - fz;
        unsigned ux = (unsigned)fx, uy = (unsigned)fy, uz = (unsigned)fz;

        unsigned hX[2] = {ux, ux + 1u};
        unsigned hY[2] = {uy * P1, (uy + 1u) * P1};
        unsigned hZ[2] = {uz * P2, (uz + 1u) * P2};
        float wX[2] = {1.0f - wx, wx};
        float wY[2] = {1.0f - wy, wy};
        float wZ[2] = {1.0f - wz, wz};

        const float2* base = (const float2*)(table) + (size_t)l * TSZ;

        float2 f[8];
        float  wt[8];
#pragma unroll
        for (int c = 0; c < 8; c++) {
            int bx = (c >> 2) & 1, by = (c >> 1) & 1, bz = c & 1;
            unsigned idx = (hX[bx] ^ hY[by] ^ hZ[bz]) & (TSZ - 1u);
            f[c]  = __ldg(base + idx);
            wt[c] = wX[bx] * wY[by] * wZ[bz];
        }
        float a0 = 0.0f, a1 = 0.0f;
#pragma unroll
        for (int c = 0; c < 8; c++) {
            a0 = fmaf(f[c].x, wt[c], a0);
            a1 = fmaf(f[c].y, wt[c], a1);
        }
        enc[2 * l + 0] = a0;
        enc[2 * l + 1] = a1;
    }

    // ---- SH3 ----
    float dx = dirs[i * 3 + 0];
    float dy = dirs[i * 3 + 1];
    float dz = dirs[i * 3 + 2];
    float sh[9];
    sh[0] = 0.28209479177387814f;
    sh[1] = -0.48860251190291987f * dy;
    sh[2] =  0.48860251190291987f * dz;
    sh[3] = -0.48860251190291987f * dx;
    sh[4] =  1.0925484305920792f  * dx * dy;
    sh[5] = -1.0925484305920792f  * dy * dz;
    sh[6] =  0.31539156525252005f * (3.0f * dz * dz - 1.0f);
    sh[7] = -1.0925484305920792f  * dx * dz;
    sh[8] =  0.5462742152960396f  * (dx * dx - dy * dy);

    // ---- feature MLP ----
    float h0[64], h1[64];
    dense<48, 64, true>(enc, h0, s + OFF_FW0, s + OFF_FB0);
    dense<64, 64, true>(h0,  h1, s + OFF_FW1, s + OFF_FB1);
    dense<64, 64, true>(h1,  h0, s + OFF_FW2, s + OFF_FB2);
    float fad[68];
    dense<64, 68, false>(h0, fad, s + OFF_FW3, s + OFF_FB3);

    float density = softplus_f(fad[0]);

    float xin[73];
#pragma unroll
    for (int j = 0; j < 64; j++) xin[j] = gelu_exact(fad[1 + j]);
#pragma unroll
    for (int j = 0; j < 9; j++)  xin[64 + j] = sh[j];

    dense<73, 64, true>(xin, h1, s + OFF_RW0, s + OFF_RB0);
    dense<64, 64, true>(h1,  h0, s + OFF_RW1, s + OFF_RB1);
    float rgb[4];
    dense<64, 4, false>(h0, rgb, s + OFF_RW2, s + OFF_RB2);

    out[i * 3 + 0] = sigmoid_f(rgb[0]);
    out[i * 3 + 1] = sigmoid_f(rgb[1]);
    out[i * 3 + 2] = sigmoid_f(rgb[2]);
    out[(size_t)3 * n + i] = density;
}

extern "C" void kernel_launch(void* const* d_in, const int* in_sizes, int n_in,
                              void* d_out, int out_size)
{
    const float* pts   = (const float*)d_in[0];
    const float* dirs  = (const float*)d_in[1];
    const float* table = (const float*)d_in[2];

    WPtrs prm;
    for (int a = 0; a < 14; a++) prm.w[a] = (const float*)d_in[3 + a];

    int n = in_sizes[0] / 3;

    ResArr res;
    double b = exp((log(2048.0) - log(16.0)) / 23.0);
    for (int l = 0; l < LVLS; l++)
        res.r[l] = (float)floor(16.0 * pow(b, (double)l));

    cudaFuncSetAttribute(nerf_fused_kernel,
                         cudaFuncAttributeMaxDynamicSharedMemorySize, SMEM_BYTES);

    int threads = 256;
    int blocks = (n + threads - 1) / threads;
    nerf_fused_kernel<<<blocks, threads, SMEM_BYTES>>>(
        pts, dirs, table, prm, res, (float*)d_out, n);
}

// round 4
// speedup vs baseline: 1.8429x; 1.8429x over previous
#include <cuda_runtime.h>
#include <cuda_bf16.h>
#include <math.h>
#include <stdint.h>

// ---------------------------------------------------------------------------
// Round 4: tensor-core fully-fused NeRF (bf16x3 split mma.sync.m16n8k16).
// Block = 256 threads (8 warps), 128 points per tile, TPB tiles per block.
// All weights staged once per block into smem as TRANSPOSED bf16 hi/lo planes.
// Each warp owns 16 rows (points) end-to-end: gather -> 7 layers -> outputs.
// Activations ping-pong between two smem plane-pairs (hi/lo bf16).
// acc = fp32; per K-tile: acc += Ahi*Bhi + Ahi*Blo + Alo*Bhi  (~1e-5 rel).
// ---------------------------------------------------------------------------

#define LVLS 24
#define TSZ  (1u << 19)
#define P1   2654435761u
#define P2   805459861u

#define XW        84      // activation plane stride (bf16 elems)
#define TILE_PTS  128
#define TPB       4       // tiles per block

// weight plane layout (u16 elems), transposed Wt[n][k], stride KP
#define WPLANE 26400
#define WOFF_L0 0         // 64x50 (K=48)
#define WOFF_L1 3200      // 64x66 (K=64)
#define WOFF_L2 7424      // 64x66
#define WOFF_L3 11648     // 72x66 (N 65->72)
#define WOFF_R0 16400     // 64x82 (K 73->80)
#define WOFF_R1 21648     // 64x66
#define WOFF_R2 25872     //  8x66 (N 3->8)

// bias offsets (fp32 elems): sizes 64,64,64,72,64,64,8
#define BOFF_L0 0
#define BOFF_L1 64
#define BOFF_L2 128
#define BOFF_L3 192
#define BOFF_R0 264
#define BOFF_R1 328
#define BOFF_R2 392
#define BIAS_FLOATS 400

// smem byte offsets
#define SO_WHI  0
#define SO_WLO  (WPLANE * 2)                    // 52800
#define SO_BIAS (WPLANE * 4)                    // 105600
#define SO_XAHI (SO_BIAS + BIAS_FLOATS * 4)     // 107200
#define XPLANE_B (TILE_PTS * XW * 2)            // 21504
#define SO_XALO (SO_XAHI + XPLANE_B)
#define SO_XBHI (SO_XALO + XPLANE_B)
#define SO_XBLO (SO_XBHI + XPLANE_B)
#define SMEM_BYTES (SO_XBLO + XPLANE_B)         // 193216

struct ResArr { float r[LVLS]; };
struct WPtrs  { const float* w[14]; };

typedef unsigned short u16;
typedef unsigned int   u32;

__device__ __forceinline__ float gelu_exact(float x) {
    return 0.5f * x * (1.0f + erff(x * 0.70710678118654752440f));
}
__device__ __forceinline__ float softplus_f(float x) {
    return fmaxf(x, 0.0f) + log1pf(expf(-fabsf(x)));
}
__device__ __forceinline__ float sigmoid_f(float x) {
    return 1.0f / (1.0f + expf(-x));
}

#define MMA_BF16(d, a0, a1, a2, a3, b0, b1)                                   \
    asm volatile(                                                             \
        "mma.sync.aligned.m16n8k16.row.col.f32.bf16.bf16.f32 "                \
        "{%0,%1,%2,%3}, {%4,%5,%6,%7}, {%8,%9}, {%0,%1,%2,%3};"               \
        : "+f"(d[0]), "+f"(d[1]), "+f"(d[2]), "+f"(d[3])                      \
        : "r"(a0), "r"(a1), "r"(a2), "r"(a3), "r"(b0), "r"(b1))

// split v into bf16 hi + bf16 lo (residual)
__device__ __forceinline__ void bf16_split(float v, u16& hi, u16& lo) {
    __nv_bfloat16 h = __float2bfloat16_rn(v);
    float r = v - __bfloat162float(h);
    __nv_bfloat16 l = __float2bfloat16_rn(r);
    hi = __bfloat16_as_ushort(h);
    lo = __bfloat16_as_ushort(l);
}

// packed store of two adjacent columns (c even) into hi/lo planes
__device__ __forceinline__ void split_store2(u16* phi, u16* plo,
                                             float v0, float v1) {
    u16 h0, l0, h1, l1;
    bf16_split(v0, h0, l0);
    bf16_split(v1, h1, l1);
    *(u32*)phi = (u32)h0 | ((u32)h1 << 16);
    *(u32*)plo = (u32)l0 | ((u32)l1 << 16);
}

__device__ __forceinline__ void split_store1(u16* phi, u16* plo, float v) {
    u16 h, l;
    bf16_split(v, h, l);
    *phi = h;
    *plo = l;
}

// ---- one dense layer on the tensor pipe ----
template<int KT, int NT, int KP>
__device__ __forceinline__ void run_layer(const u16* __restrict__ xhi,
                                          const u16* __restrict__ xlo,
                                          const u16* __restrict__ whi,
                                          const u16* __restrict__ wlo,
                                          const float* __restrict__ bias,
                                          float (&acc)[NT][4], int lane)
{
    const int qr = lane >> 2, qm = lane & 3;
#pragma unroll
    for (int nt = 0; nt < NT; nt++) {
        float b0 = bias[nt * 8 + 2 * qm];
        float b1 = bias[nt * 8 + 2 * qm + 1];
        acc[nt][0] = b0; acc[nt][1] = b1;
        acc[nt][2] = b0; acc[nt][3] = b1;
    }
    const u16* pa  = xhi + qr * XW + 2 * qm;
    const u16* pal = xlo + qr * XW + 2 * qm;
#pragma unroll
    for (int kt = 0; kt < KT; kt++) {
        u32 ah0 = *(const u32*)(pa  + kt * 16);
        u32 ah1 = *(const u32*)(pa  + kt * 16 + 8 * XW);
        u32 ah2 = *(const u32*)(pa  + kt * 16 + 8);
        u32 ah3 = *(const u32*)(pa  + kt * 16 + 8 * XW + 8);
        u32 al0 = *(const u32*)(pal + kt * 16);
        u32 al1 = *(const u32*)(pal + kt * 16 + 8 * XW);
        u32 al2 = *(const u32*)(pal + kt * 16 + 8);
        u32 al3 = *(const u32*)(pal + kt * 16 + 8 * XW + 8);
#pragma unroll
        for (int nt = 0; nt < NT; nt++) {
            const u16* pb  = whi + (nt * 8 + qr) * KP + 2 * qm + kt * 16;
            const u16* pbl = wlo + (nt * 8 + qr) * KP + 2 * qm + kt * 16;
            u32 bh0 = *(const u32*)(pb);
            u32 bh1 = *(const u32*)(pb + 8);
            u32 bl0 = *(const u32*)(pbl);
            u32 bl1 = *(const u32*)(pbl + 8);
            MMA_BF16(acc[nt], ah0, ah1, ah2, ah3, bh0, bh1);
            MMA_BF16(acc[nt], ah0, ah1, ah2, ah3, bl0, bl1);
            MMA_BF16(acc[nt], al0, al1, al2, al3, bh0, bh1);
        }
    }
}

template<int NT>
__device__ __forceinline__ void store_acts_gelu(u16* __restrict__ yhi,
                                                u16* __restrict__ ylo,
                                                float (&acc)[NT][4], int lane)
{
    const int qr = lane >> 2, qm = lane & 3;
#pragma unroll
    for (int nt = 0; nt < NT; nt++) {
        int c = nt * 8 + 2 * qm;
        split_store2(yhi + qr * XW + c,       ylo + qr * XW + c,
                     gelu_exact(acc[nt][0]),  gelu_exact(acc[nt][1]));
        split_store2(yhi + (qr + 8) * XW + c, ylo + (qr + 8) * XW + c,
                     gelu_exact(acc[nt][2]),  gelu_exact(acc[nt][3]));
    }
}

// ---- staging helpers ----
__device__ void stage_w(const float* __restrict__ g, u16* hi, u16* lo,
                        int realK, int realN, int K, int NPAD, int KP, int tid)
{
    for (int idx = tid; idx < NPAD * K; idx += 256) {
        int nn = idx / K, kk = idx % K;
        float v = (kk < realK && nn < realN) ? g[kk * realN + nn] : 0.0f;
        u16 h, l;
        bf16_split(v, h, l);
        hi[nn * KP + kk] = h;
        lo[nn * KP + kk] = l;
    }
}
__device__ void stage_b(const float* __restrict__ g, float* dst,
                        int realN, int NPAD, int tid)
{
    for (int i = tid; i < NPAD; i += 256)
        dst[i] = (i < realN) ? g[i] : 0.0f;
}

__global__ void __launch_bounds__(256, 1)
nerf_tc_kernel(const float* __restrict__ pts,
               const float* __restrict__ dirs,
               const float* __restrict__ table,
               WPtrs prm, ResArr res,
               float* __restrict__ out, int n)
{
    extern __shared__ char smem[];
    u16*   whi  = (u16*)(smem + SO_WHI);
    u16*   wlo  = (u16*)(smem + SO_WLO);
    float* bias = (float*)(smem + SO_BIAS);
    u16*   xahi = (u16*)(smem + SO_XAHI);
    u16*   xalo = (u16*)(smem + SO_XALO);
    u16*   xbhi = (u16*)(smem + SO_XBHI);
    u16*   xblo = (u16*)(smem + SO_XBLO);

    const int tid  = threadIdx.x;
    const int warp = tid >> 5;
    const int lane = tid & 31;
    const int qr = lane >> 2, qm = lane & 3;

    // ---- stage all weights/biases once per block ----
    stage_w(prm.w[0],  whi + WOFF_L0, wlo + WOFF_L0, 48, 64, 48, 64, 50, tid);
    stage_w(prm.w[2],  whi + WOFF_L1, wlo + WOFF_L1, 64, 64, 64, 64, 66, tid);
    stage_w(prm.w[4],  whi + WOFF_L2, wlo + WOFF_L2, 64, 64, 64, 64, 66, tid);
    stage_w(prm.w[6],  whi + WOFF_L3, wlo + WOFF_L3, 64, 65, 64, 72, 66, tid);
    stage_w(prm.w[8],  whi + WOFF_R0, wlo + WOFF_R0, 73, 64, 80, 64, 82, tid);
    stage_w(prm.w[10], whi + WOFF_R1, wlo + WOFF_R1, 64, 64, 64, 64, 66, tid);
    stage_w(prm.w[12], whi + WOFF_R2, wlo + WOFF_R2, 64,  3, 64,  8, 66, tid);
    stage_b(prm.w[1],  bias + BOFF_L0, 64, 64, tid);
    stage_b(prm.w[3],  bias + BOFF_L1, 64, 64, tid);
    stage_b(prm.w[5],  bias + BOFF_L2, 64, 64, tid);
    stage_b(prm.w[7],  bias + BOFF_L3, 65, 72, tid);
    stage_b(prm.w[9],  bias + BOFF_R0, 64, 64, tid);
    stage_b(prm.w[11], bias + BOFF_R1, 64, 64, tid);
    stage_b(prm.w[13], bias + BOFF_R2,  3,  8, tid);
    __syncthreads();

    // warp-row bases for activation planes
    u16* Ahi = xahi + warp * 16 * XW;
    u16* Alo = xalo + warp * 16 * XW;
    u16* Bhi = xbhi + warp * 16 * XW;
    u16* Blo = xblo + warp * 16 * XW;

    // zero XA pad cols 73..83 (needed for R0 k-tile 4; survives all tiles)
    if (lane < 16) {
#pragma unroll
        for (int c = 73; c < XW; c++) {
            Ahi[lane * XW + c] = 0;
            Alo[lane * XW + c] = 0;
        }
    }
    __syncwarp();

    for (int t = 0; t < TPB; t++) {
        const int tile = blockIdx.x * TPB + t;
        const int base = tile * TILE_PTS;

        // ---- hash-grid gather: 2 threads per point, 12 levels each ----
        // plocal = tid>>1 keeps each point's rows within its own warp.
        {
            const int plocal = tid >> 1;          // 0..127
            const int gpt = base + plocal;
            const int row = plocal & 15;          // row within warp's 16
            float px = pts[gpt * 3 + 0];
            float py = pts[gpt * 3 + 1];
            float pz = pts[gpt * 3 + 2];
            float x0 = (px + 1.0f) * 0.5f;
            float y0 = (py + 1.0f) * 0.5f;
            float z0 = (pz + 1.0f) * 0.5f;
            const int l0 = (tid & 1) * 12;
#pragma unroll 1
            for (int l = l0; l < l0 + 12; l++) {
                float rl = res.r[l];
                float posx = x0 * rl, posy = y0 * rl, posz = z0 * rl;
                float fx = floorf(posx), fy = floorf(posy), fz = floorf(posz);
                float wx = posx - fx, wy = posy - fy, wz = posz - fz;
                unsigned ux = (unsigned)fx, uy = (unsigned)fy, uz = (unsigned)fz;
                unsigned hX[2] = {ux, ux + 1u};
                unsigned hY[2] = {uy * P1, (uy + 1u) * P1};
                unsigned hZ[2] = {uz * P2, (uz + 1u) * P2};
                float wX[2] = {1.0f - wx, wx};
                float wY[2] = {1.0f - wy, wy};
                float wZ[2] = {1.0f - wz, wz};
                const float2* tb = (const float2*)table + (size_t)l * TSZ;
                float2 f[8]; float wt[8];
#pragma unroll
                for (int c = 0; c < 8; c++) {
                    int bx = (c >> 2) & 1, by = (c >> 1) & 1, bz = c & 1;
                    unsigned idx = (hX[bx] ^ hY[by] ^ hZ[bz]) & (TSZ - 1u);
                    f[c]  = __ldg(tb + idx);
                    wt[c] = wX[bx] * wY[by] * wZ[bz];
                }
                float a0 = 0.0f, a1 = 0.0f;
#pragma unroll
                for (int c = 0; c < 8; c++) {
                    a0 = fmaf(f[c].x, wt[c], a0);
                    a1 = fmaf(f[c].y, wt[c], a1);
                }
                split_store2(Ahi + row * XW + 2 * l, Alo + row * XW + 2 * l,
                             a0, a1);
            }
        }
        __syncwarp();

        // ---- feature MLP ----
        {
            float acc[8][4];
            run_layer<3, 8, 50>(Ahi, Alo, whi + WOFF_L0, wlo + WOFF_L0,
                                bias + BOFF_L0, acc, lane);
            store_acts_gelu<8>(Bhi, Blo, acc, lane);
        }
        __syncwarp();
        {
            float acc[8][4];
            run_layer<4, 8, 66>(Bhi, Blo, whi + WOFF_L1, wlo + WOFF_L1,
                                bias + BOFF_L1, acc, lane);
            store_acts_gelu<8>(Ahi, Alo, acc, lane);
        }
        __syncwarp();
        {
            float acc[8][4];
            run_layer<4, 8, 66>(Ahi, Alo, whi + WOFF_L2, wlo + WOFF_L2,
                                bias + BOFF_L2, acc, lane);
            store_acts_gelu<8>(Bhi, Blo, acc, lane);
        }
        __syncwarp();
        {
            float acc[9][4];
            run_layer<4, 9, 66>(Bhi, Blo, whi + WOFF_L3, wlo + WOFF_L3,
                                bias + BOFF_L3, acc, lane);
            // emit: col 0 -> density, cols 1..64 -> gelu -> XA cols 0..63
#pragma unroll
            for (int nt = 0; nt < 9; nt++) {
                int c = nt * 8 + 2 * qm;
#pragma unroll
                for (int j = 0; j < 4; j++) {
                    int col  = c + (j & 1);
                    int lrow = qr + ((j >> 1) ? 8 : 0);
                    float v = acc[nt][j];
                    if (col == 0) {
                        out[(size_t)3 * n + (base + warp * 16 + lrow)] =
                            softplus_f(v);
                    } else if (col <= 64) {
                        float g = gelu_exact(v);
                        split_store1(Ahi + lrow * XW + (col - 1),
                                     Alo + lrow * XW + (col - 1), g);
                    }
                }
            }
        }
        // sh -> XA cols 64..72 (lanes 0..15, one row each)
        if (lane < 16) {
            int lrow = lane;
            int gpt = base + warp * 16 + lrow;
            float dx = dirs[gpt * 3 + 0];
            float dy = dirs[gpt * 3 + 1];
            float dz = dirs[gpt * 3 + 2];
            float sh[9];
            sh[0] = 0.28209479177387814f;
            sh[1] = -0.48860251190291987f * dy;
            sh[2] =  0.48860251190291987f * dz;
            sh[3] = -0.48860251190291987f * dx;
            sh[4] =  1.0925484305920792f  * dx * dy;
            sh[5] = -1.0925484305920792f  * dy * dz;
            sh[6] =  0.31539156525252005f * (3.0f * dz * dz - 1.0f);
            sh[7] = -1.0925484305920792f  * dx * dz;
            sh[8] =  0.5462742152960396f  * (dx * dx - dy * dy);
#pragma unroll
            for (int j = 0; j < 9; j++)
                split_store1(Ahi + lrow * XW + 64 + j,
                             Alo + lrow * XW + 64 + j, sh[j]);
        }
        __syncwarp();

        // ---- RGB MLP ----
        {
            float acc[8][4];
            run_layer<5, 8, 82>(Ahi, Alo, whi + WOFF_R0, wlo + WOFF_R0,
                                bias + BOFF_R0, acc, lane);
            store_acts_gelu<8>(Bhi, Blo, acc, lane);
        }
        __syncwarp();
        {
            float acc[8][4];
            run_layer<4, 8, 66>(Bhi, Blo, whi + WOFF_R1, wlo + WOFF_R1,
                                bias + BOFF_R1, acc, lane);
            store_acts_gelu<8>(Ahi, Alo, acc, lane);
        }
        __syncwarp();
        {
            float acc[1][4];
            run_layer<4, 1, 66>(Ahi, Alo, whi + WOFF_R2, wlo + WOFF_R2,
                                bias + BOFF_R2, acc, lane);
            int pt0 = base + warp * 16 + qr;
            int pt1 = pt0 + 8;
            if (qm == 0) {
                out[pt0 * 3 + 0] = sigmoid_f(acc[0][0]);
                out[pt0 * 3 + 1] = sigmoid_f(acc[0][1]);
                out[pt1 * 3 + 0] = sigmoid_f(acc[0][2]);
                out[pt1 * 3 + 1] = sigmoid_f(acc[0][3]);
            } else if (qm == 1) {
                out[pt0 * 3 + 2] = sigmoid_f(acc[0][0]);
                out[pt1 * 3 + 2] = sigmoid_f(acc[0][2]);
            }
        }
        __syncwarp();
    }
}

extern "C" void kernel_launch(void* const* d_in, const int* in_sizes, int n_in,
                              void* d_out, int out_size)
{
    const float* pts   = (const float*)d_in[0];
    const float* dirs  = (const float*)d_in[1];
    const float* table = (const float*)d_in[2];

    WPtrs prm;
    for (int a = 0; a < 14; a++) prm.w[a] = (const float*)d_in[3 + a];

    int n = in_sizes[0] / 3;

    ResArr res;
    double b = exp((log(2048.0) - log(16.0)) / 23.0);
    for (int l = 0; l < LVLS; l++)
        res.r[l] = (float)floor(16.0 * pow(b, (double)l));

    cudaFuncSetAttribute(nerf_tc_kernel,
                         cudaFuncAttributeMaxDynamicSharedMemorySize, SMEM_BYTES);

    int ntiles = n / TILE_PTS;            // 4096
    int blocks = ntiles / TPB;            // 1024
    nerf_tc_kernel<<<blocks, 256, SMEM_BYTES>>>(
        pts, dirs, table, prm, res, (float*)d_out, n);
}